// round 2
// baseline (speedup 1.0000x reference)
#include <cuda_runtime.h>

// TreeNLLLoss, single fused kernel:
//   loss = sum_e edge_pot[e, 16*tc+tp] + sum_e unary[child_e, tc] + unary[root, l_root]
//   out  = -(loss - partition)
// E = 1,000,000 edges, N = 1,000,001 nodes, C = 16.

#define C 16
#define EPT 4
#define THREADS 256
#define MAX_BLOCKS 4096

__device__ float    g_partials[MAX_BLOCKS];
__device__ unsigned g_count = 0;   // always returns to 0 (last block resets)

__global__ void __launch_bounds__(THREADS)
fused_kernel(const float* __restrict__ edge_pot,
             const float* __restrict__ unary,
             const int*   __restrict__ labels,
             const int*   __restrict__ child_idx,
             const int*   __restrict__ parent_idx,
             const int*   __restrict__ root_idx,
             const float* __restrict__ partition,
             float* __restrict__ out,
             int E)
{
    const int tid  = blockIdx.x * THREADS + threadIdx.x;
    const int base = tid * EPT;

    float s = 0.0f;

    if (base + EPT <= E) {
        // Level 0: vectorized streamed index loads (int4, coalesced)
        int4 c4 = __ldg((const int4*)child_idx  + tid);
        int4 p4 = __ldg((const int4*)parent_idx + tid);
        int c[EPT] = {c4.x, c4.y, c4.z, c4.w};
        int p[EPT] = {p4.x, p4.y, p4.z, p4.w};

        // Level 1: label gathers (batched -> MLP=8)
        int tc[EPT], tp[EPT];
        #pragma unroll
        for (int j = 0; j < EPT; j++) {
            tc[j] = __ldg(&labels[c[j]]);
            tp[j] = __ldg(&labels[p[j]]);
        }

        // Level 2: potential gathers (batched -> MLP=8)
        float ep[EPT], cu[EPT];
        #pragma unroll
        for (int j = 0; j < EPT; j++) {
            ep[j] = __ldg(&edge_pot[(size_t)(base + j) * (C * C) + tc[j] * C + tp[j]]);
            cu[j] = __ldg(&unary[(size_t)c[j] * C + tc[j]]);
        }

        #pragma unroll
        for (int j = 0; j < EPT; j++) s += ep[j] + cu[j];
    } else {
        // tail (only the last partial thread takes this path)
        for (int j = 0; j < EPT; j++) {
            int e = base + j;
            if (e < E) {
                int ci = __ldg(&child_idx[e]);
                int pi = __ldg(&parent_idx[e]);
                int tc = __ldg(&labels[ci]);
                int tp = __ldg(&labels[pi]);
                s += __ldg(&edge_pot[(size_t)e * (C * C) + tc * C + tp]);
                s += __ldg(&unary[(size_t)ci * C + tc]);
            }
        }
    }

    // ── block reduce (warp shuffle -> shared -> warp 0) ──
    #pragma unroll
    for (int off = 16; off > 0; off >>= 1)
        s += __shfl_down_sync(0xffffffffu, s, off);

    __shared__ float warp_sums[THREADS / 32];
    const int lane = threadIdx.x & 31;
    const int wid  = threadIdx.x >> 5;
    if (lane == 0) warp_sums[wid] = s;
    __syncthreads();

    if (wid == 0) {
        float t = (lane < THREADS / 32) ? warp_sums[lane] : 0.0f;
        #pragma unroll
        for (int off = 4; off > 0; off >>= 1)
            t += __shfl_down_sync(0xffffffffu, t, off);
        if (lane == 0) g_partials[blockIdx.x] = t;
    }

    // ── last-block-done finalize ──
    __shared__ bool is_last;
    __threadfence();  // partial store visible before ticket
    if (threadIdx.x == 0) {
        unsigned ticket = atomicAdd(&g_count, 1u);
        is_last = (ticket == gridDim.x - 1);
    }
    __syncthreads();

    if (is_last) {
        // all partials are in L2 now; read bypassing L1
        double acc = 0.0;
        for (int i = threadIdx.x; i < (int)gridDim.x; i += THREADS)
            acc += (double)__ldcg(&g_partials[i]);

        // reduce doubles across the block
        #pragma unroll
        for (int off = 16; off > 0; off >>= 1)
            acc += __shfl_down_sync(0xffffffffu, acc, off);

        __shared__ double dwarp[THREADS / 32];
        if (lane == 0) dwarp[wid] = acc;
        __syncthreads();

        if (wid == 0) {
            double t = (lane < THREADS / 32) ? dwarp[lane] : 0.0;
            #pragma unroll
            for (int off = 4; off > 0; off >>= 1)
                t += __shfl_down_sync(0xffffffffu, t, off);
            if (lane == 0) {
                int r = __ldg(root_idx);
                float root_unary = __ldg(&unary[(size_t)r * C + __ldg(&labels[r])]);
                double loss = t + (double)root_unary;
                out[0] = -(float)(loss - (double)__ldg(partition));
                g_count = 0;   // reset for next replay (deterministic)
            }
        }
    }
}

extern "C" void kernel_launch(void* const* d_in, const int* in_sizes, int n_in,
                              void* d_out, int out_size)
{
    const float* edge_pot   = (const float*)d_in[0];
    const float* unary      = (const float*)d_in[1];
    const int*   labels     = (const int*)d_in[2];
    const int*   child_idx  = (const int*)d_in[3];
    const int*   parent_idx = (const int*)d_in[4];
    const int*   root_idx   = (const int*)d_in[5];
    const float* partition  = (const float*)d_in[6];
    float* out = (float*)d_out;

    int E = in_sizes[3];

    int per_block = THREADS * EPT;
    int blocks = (E + per_block - 1) / per_block;
    if (blocks > MAX_BLOCKS) blocks = MAX_BLOCKS;  // safety (E=1e6 -> 977)

    fused_kernel<<<blocks, THREADS>>>(edge_pot, unary, labels, child_idx,
                                      parent_idx, root_idx, partition, out, E);
}

// round 3
// speedup vs baseline: 1.2399x; 1.2399x over previous
#include <cuda_runtime.h>

// TreeNLLLoss, single fused kernel:
//   loss = sum_e edge_pot[e, 16*tc+tp] + sum_e unary[child_e, tc] + unary[root, l_root]
//   out  = -(loss - partition)
// E = 1,000,000 edges, N = 1,000,001 nodes, C = 16.
//
// Cache strategy: edge_pot lines are touched once per replay (1M x 128B fills
// ~= L2 capacity) -> load with __ldcs (evict-first) so they don't thrash the
// reusable arrays (unary 64MB + labels 4MB + idx 8MB = 76MB, L2-resident).

#define C 16
#define EPT 8
#define THREADS 256
#define MAX_BLOCKS 4096

__device__ float    g_partials[MAX_BLOCKS];
__device__ unsigned g_count = 0;   // always returns to 0 (last block resets)

__global__ void __launch_bounds__(THREADS)
fused_kernel(const float* __restrict__ edge_pot,
             const float* __restrict__ unary,
             const int*   __restrict__ labels,
             const int*   __restrict__ child_idx,
             const int*   __restrict__ parent_idx,
             const int*   __restrict__ root_idx,
             const float* __restrict__ partition,
             float* __restrict__ out,
             int E)
{
    const int tid  = blockIdx.x * THREADS + threadIdx.x;
    const int base = tid * EPT;

    float s = 0.0f;

    if (base + EPT <= E) {
        // Level 0: vectorized streamed index loads (two int4 per array)
        int4 c4a = __ldg((const int4*)child_idx  + 2 * tid);
        int4 c4b = __ldg((const int4*)child_idx  + 2 * tid + 1);
        int4 p4a = __ldg((const int4*)parent_idx + 2 * tid);
        int4 p4b = __ldg((const int4*)parent_idx + 2 * tid + 1);
        int c[EPT] = {c4a.x, c4a.y, c4a.z, c4a.w, c4b.x, c4b.y, c4b.z, c4b.w};
        int p[EPT] = {p4a.x, p4a.y, p4a.z, p4a.w, p4b.x, p4b.y, p4b.z, p4b.w};

        // Level 1: label gathers (L2-resident, batched -> MLP=16)
        int tc[EPT], tp[EPT];
        #pragma unroll
        for (int j = 0; j < EPT; j++) {
            tc[j] = __ldg(&labels[c[j]]);
            tp[j] = __ldg(&labels[p[j]]);
        }

        // Level 2: potential gathers (batched -> MLP=16)
        //   edge_pot: streaming / evict-first (one-shot lines, don't pollute L2)
        //   unary:    default caching (keep resident)
        float ep[EPT], cu[EPT];
        #pragma unroll
        for (int j = 0; j < EPT; j++) {
            ep[j] = __ldcs(&edge_pot[(size_t)(base + j) * (C * C) + tc[j] * C + tp[j]]);
            cu[j] = __ldg(&unary[(size_t)c[j] * C + tc[j]]);
        }

        #pragma unroll
        for (int j = 0; j < EPT; j++) s += ep[j] + cu[j];
    } else {
        // tail (unused for E = 1e6, kept for safety)
        for (int j = 0; j < EPT; j++) {
            int e = base + j;
            if (e < E) {
                int ci = __ldg(&child_idx[e]);
                int pi = __ldg(&parent_idx[e]);
                int tc = __ldg(&labels[ci]);
                int tp = __ldg(&labels[pi]);
                s += __ldcs(&edge_pot[(size_t)e * (C * C) + tc * C + tp]);
                s += __ldg(&unary[(size_t)ci * C + tc]);
            }
        }
    }

    // ── block reduce (warp shuffle -> shared -> warp 0) ──
    #pragma unroll
    for (int off = 16; off > 0; off >>= 1)
        s += __shfl_down_sync(0xffffffffu, s, off);

    __shared__ float warp_sums[THREADS / 32];
    const int lane = threadIdx.x & 31;
    const int wid  = threadIdx.x >> 5;
    if (lane == 0) warp_sums[wid] = s;
    __syncthreads();

    if (wid == 0) {
        float t = (lane < THREADS / 32) ? warp_sums[lane] : 0.0f;
        #pragma unroll
        for (int off = 4; off > 0; off >>= 1)
            t += __shfl_down_sync(0xffffffffu, t, off);
        if (lane == 0) g_partials[blockIdx.x] = t;
    }

    // ── last-block-done finalize ──
    __shared__ bool is_last;
    __threadfence();  // partial store visible before ticket
    if (threadIdx.x == 0) {
        unsigned ticket = atomicAdd(&g_count, 1u);
        is_last = (ticket == gridDim.x - 1);
    }
    __syncthreads();

    if (is_last) {
        double acc = 0.0;
        for (int i = threadIdx.x; i < (int)gridDim.x; i += THREADS)
            acc += (double)__ldcg(&g_partials[i]);

        #pragma unroll
        for (int off = 16; off > 0; off >>= 1)
            acc += __shfl_down_sync(0xffffffffu, acc, off);

        __shared__ double dwarp[THREADS / 32];
        if (lane == 0) dwarp[wid] = acc;
        __syncthreads();

        if (wid == 0) {
            double t = (lane < THREADS / 32) ? dwarp[lane] : 0.0;
            #pragma unroll
            for (int off = 4; off > 0; off >>= 1)
                t += __shfl_down_sync(0xffffffffu, t, off);
            if (lane == 0) {
                int r = __ldg(root_idx);
                float root_unary = __ldg(&unary[(size_t)r * C + __ldg(&labels[r])]);
                double loss = t + (double)root_unary;
                out[0] = -(float)(loss - (double)__ldg(partition));
                g_count = 0;   // reset for next replay (deterministic)
            }
        }
    }
}

extern "C" void kernel_launch(void* const* d_in, const int* in_sizes, int n_in,
                              void* d_out, int out_size)
{
    const float* edge_pot   = (const float*)d_in[0];
    const float* unary      = (const float*)d_in[1];
    const int*   labels     = (const int*)d_in[2];
    const int*   child_idx  = (const int*)d_in[3];
    const int*   parent_idx = (const int*)d_in[4];
    const int*   root_idx   = (const int*)d_in[5];
    const float* partition  = (const float*)d_in[6];
    float* out = (float*)d_out;

    int E = in_sizes[3];

    int per_block = THREADS * EPT;
    int blocks = (E + per_block - 1) / per_block;
    if (blocks > MAX_BLOCKS) blocks = MAX_BLOCKS;  // safety (E=1e6 -> 489)

    fused_kernel<<<blocks, THREADS>>>(edge_pot, unary, labels, child_idx,
                                      parent_idx, root_idx, partition, out, E);
}